// round 3
// baseline (speedup 1.0000x reference)
#include <cuda_runtime.h>

#define BB   2
#define NN   16384
#define MM   4096
#define CF   256
#define CT   128
#define CP   64
#define CTOT 384        // CF + CT interpolated channels
#define TILE 2048       // ref points per smem tile in knn kernel
#define PTS  16         // query points per block in interp kernel

// Scratch (device globals: no allocation allowed)
__device__ int   g_idx[BB * NN * 3];
__device__ float g_w[BB * NN * 3];
__device__ float g_featT[(size_t)BB * MM * CTOT];   // [B][M][384] channel-contiguous

// ---------------------------------------------------------------------------
// Kernel 1: 3-NN search. ONE query point per lane; all 32 lanes of a warp
// scan the same candidate each iteration -> the LDS.128 is a broadcast
// (16B/warp-op on the crossbar instead of 512B). Distances tracked in the
// shifted space d' = |r|^2 - 2 p.r (|p|^2 folded out of the loop).
// ---------------------------------------------------------------------------
__global__ __launch_bounds__(128) void knn_kernel(const float* __restrict__ coords,
                                                  const float* __restrict__ refc) {
    __shared__ float4 sref[TILE];   // {rx, ry, rz, |r|^2}  (32 KB)

    int tid = threadIdx.x;
    int b   = blockIdx.x >> 7;              // 128 blocks per batch
    int pt  = ((blockIdx.x & 127) << 7) + tid;   // 128 points per block

    const float* cp = coords + ((size_t)(b * NN + pt)) * 3;
    float px = cp[0], py = cp[1], pz = cp[2];
    float pp  = px * px + py * py + pz * pz;
    float px2 = -2.0f * px, py2 = -2.0f * py, pz2 = -2.0f * pz;

    float d0 = 1e30f, d1 = 1e30f, d2 = 1e30f;   // shifted-space distances
    int   i0 = 0, i1 = 0, i2 = 0;

    const float* rb = refc + (size_t)b * MM * 3;

    for (int t = 0; t < MM; t += TILE) {
        for (int m = tid; m < TILE; m += 128) {
            const float* r = rb + (size_t)(t + m) * 3;
            float rx = r[0], ry = r[1], rz = r[2];
            sref[m] = make_float4(rx, ry, rz, rx * rx + ry * ry + rz * rz);
        }
        __syncthreads();

        #pragma unroll 8
        for (int m = 0; m < TILE; m++) {
            float4 r = sref[m];
            float dp = fmaf(r.x, px2, fmaf(r.y, py2, fmaf(r.z, pz2, r.w)));
            if (dp < d2) {
                int gm = t + m;
                if (dp < d1) {
                    d2 = d1; i2 = i1;
                    if (dp < d0) { d1 = d0; i1 = i0; d0 = dp; i0 = gm; }
                    else         { d1 = dp; i1 = gm; }
                } else { d2 = dp; i2 = gm; }
            }
        }
        __syncthreads();
    }

    // back to true squared distances
    d0 += pp; d1 += pp; d2 += pp;
    float w0 = 1.0f / (d0 + 1e-8f);
    float w1 = 1.0f / (d1 + 1e-8f);
    float w2 = 1.0f / (d2 + 1e-8f);
    float inv = 1.0f / (w0 + w1 + w2);
    size_t base = ((size_t)(b * NN + pt)) * 3;
    g_w[base]     = w0 * inv;
    g_w[base + 1] = w1 * inv;
    g_w[base + 2] = w2 * inv;
    g_idx[base]     = i0;
    g_idx[base + 1] = i1;
    g_idx[base + 2] = i2;
}

// ---------------------------------------------------------------------------
// Kernel 2: fuse ref_features [B,256,M] + ref_t_embed [B,128,M] into a
// channel-contiguous scratch g_featT [B, M, 384] via tiled 32x32 transpose.
// ---------------------------------------------------------------------------
__global__ __launch_bounds__(256) void transpose_kernel(const float* __restrict__ rf,
                                                        const float* __restrict__ rt) {
    __shared__ float tile[32][33];
    int b     = blockIdx.z;
    int mBase = blockIdx.x * 32;
    int cBase = blockIdx.y * 32;
    int tx = threadIdx.x & 31;
    int ty = threadIdx.x >> 5;   // 8 rows

    #pragma unroll
    for (int i = 0; i < 4; i++) {
        int c = cBase + ty + i * 8;
        int m = mBase + tx;
        float v;
        if (c < CF) v = rf[((size_t)b * CF + c) * MM + m];
        else        v = rt[((size_t)b * CT + (c - CF)) * MM + m];
        tile[ty + i * 8][tx] = v;
    }
    __syncthreads();
    #pragma unroll
    for (int i = 0; i < 4; i++) {
        int m = mBase + ty + i * 8;
        int c = cBase + tx;
        g_featT[((size_t)b * MM + m) * CTOT + c] = tile[tx][ty + i * 8];
    }
}

// ---------------------------------------------------------------------------
// Kernel 3: weighted gather of 3 contiguous 384-float rows per query point
// (float4 loads), staged through padded smem [nl][385] (conflict-free both
// directions) so the [B,C,N] output writes are coalesced along n.
// ---------------------------------------------------------------------------
__global__ __launch_bounds__(256) void interp_kernel(float* __restrict__ out) {
    __shared__ float sacc[PTS * (CTOT + 1)];   // [nl][385]
    __shared__ int   sidx[PTS * 3];
    __shared__ float sw[PTS * 3];

    int tid = threadIdx.x;
    int blocksPerB = NN / PTS;           // 1024
    int b  = blockIdx.x / blocksPerB;
    int n0 = (blockIdx.x % blocksPerB) * PTS;

    if (tid < PTS * 3) {
        size_t base = ((size_t)(b * NN + n0)) * 3;
        sidx[tid] = g_idx[base + tid];
        sw[tid]   = g_w[base + tid];
    }
    __syncthreads();

    const float4* ft = (const float4*)(g_featT + (size_t)b * MM * CTOT);
    const int R4 = CTOT / 4;             // 96 float4 per row

    for (int j = tid; j < PTS * R4; j += 256) {
        int nl = j / R4;
        int c4 = j - nl * R4;
        int q  = nl * 3;
        float w0 = sw[q], w1 = sw[q + 1], w2 = sw[q + 2];
        float4 a = ft[(size_t)sidx[q]     * R4 + c4];
        float4 bv = ft[(size_t)sidx[q + 1] * R4 + c4];
        float4 cv = ft[(size_t)sidx[q + 2] * R4 + c4];
        float* dst = sacc + nl * (CTOT + 1) + c4 * 4;
        dst[0] = fmaf(w0, a.x, fmaf(w1, bv.x, w2 * cv.x));
        dst[1] = fmaf(w0, a.y, fmaf(w1, bv.y, w2 * cv.y));
        dst[2] = fmaf(w0, a.z, fmaf(w1, bv.z, w2 * cv.z));
        dst[3] = fmaf(w0, a.w, fmaf(w1, bv.w, w2 * cv.w));
    }
    __syncthreads();

    float* tout = out + (size_t)BB * 320 * NN;   // t_embed block after features
    for (int j = tid; j < PTS * CTOT; j += 256) {
        int c  = j >> 4;       // / PTS
        int nl = j & 15;
        float v = sacc[nl * (CTOT + 1) + c];
        if (c < CF) out[((size_t)b * 320 + c) * NN + n0 + nl] = v;
        else        tout[((size_t)b * CT + (c - CF)) * NN + n0 + nl] = v;
    }
}

// ---------------------------------------------------------------------------
extern "C" void kernel_launch(void* const* d_in, const int* in_sizes, int n_in,
                              void* d_out, int out_size) {
    const float* coords = (const float*)d_in[0];   // [B, N, 3]
    const float* refc   = (const float*)d_in[1];   // [B, M, 3]
    const float* rf     = (const float*)d_in[2];   // [B, 256, M]
    const float* rt     = (const float*)d_in[3];   // [B, 128, M]
    const float* pf     = (const float*)d_in[4];   // [B, 64, N]
    float* out = (float*)d_out;

    knn_kernel<<<BB * NN / 128, 128>>>(coords, refc);

    dim3 tg(MM / 32, CTOT / 32, BB);
    transpose_kernel<<<tg, 256>>>(rf, rt);

    interp_kernel<<<BB * NN / PTS, 256>>>(out);

    // Skip-feature concat: channels 256..319 of the features block are a
    // contiguous copy of points_features per batch.
    for (int b = 0; b < BB; b++) {
        cudaMemcpyAsync(out + ((size_t)b * 320 + 256) * NN,
                        pf + (size_t)b * CP * NN,
                        (size_t)CP * NN * sizeof(float),
                        cudaMemcpyDeviceToDevice);
    }
}

// round 5
// speedup vs baseline: 1.3937x; 1.3937x over previous
#include <cuda_runtime.h>

#define BB   2
#define NN   16384
#define MM   4096
#define CF   256
#define CT   128
#define CP   64
#define CTOT 384        // CF + CT interpolated channels
#define SEG  4          // M-dimension split factor for knn
#define SEGM (MM / SEG) // 1024 candidates per segment
#define PTS  16         // query points per block in interp kernel

// Scratch (device globals: no allocation allowed)
__device__ float g_pd[BB * NN * SEG * 3];   // partial top-3 shifted distances
__device__ int   g_pi[BB * NN * SEG * 3];   // partial top-3 indices
__device__ int   g_idx[BB * NN * 3];
__device__ float g_w[BB * NN * 3];
__device__ float g_featT[(size_t)BB * MM * CTOT];   // [B][M][384] channel-contiguous

// ---------------------------------------------------------------------------
// Kernel 1a: partial 3-NN. One query point per lane (broadcast candidate
// loads, conflict-free), M split across SEG blocks per point-group for
// occupancy. Distances in shifted space d' = |r|^2 - 2 p.r.
// ---------------------------------------------------------------------------
__global__ __launch_bounds__(128) void knn_partial_kernel(const float* __restrict__ coords,
                                                          const float* __restrict__ refc) {
    __shared__ float4 sref[SEGM];   // {rx, ry, rz, |r|^2}  (16 KB)

    int tid  = threadIdx.x;
    int bid  = blockIdx.x;
    int seg  = bid & (SEG - 1);
    int rest = bid >> 2;                 // BB * 128 point-groups
    int b    = rest >> 7;
    int pt   = ((rest & 127) << 7) + tid;

    const float* cp = coords + ((size_t)(b * NN + pt)) * 3;
    float px = cp[0], py = cp[1], pz = cp[2];
    float px2 = -2.0f * px, py2 = -2.0f * py, pz2 = -2.0f * pz;

    const float* rb = refc + ((size_t)b * MM + seg * SEGM) * 3;
    for (int m = tid; m < SEGM; m += 128) {
        const float* r = rb + (size_t)m * 3;
        float rx = r[0], ry = r[1], rz = r[2];
        sref[m] = make_float4(rx, ry, rz, rx * rx + ry * ry + rz * rz);
    }
    __syncthreads();

    float d0 = 1e30f, d1 = 1e30f, d2 = 1e30f;   // shifted-space distances
    int   i0 = 0, i1 = 0, i2 = 0;
    int   gbase = seg * SEGM;

    #pragma unroll 8
    for (int m = 0; m < SEGM; m++) {
        float4 r = sref[m];
        float dp = fmaf(r.x, px2, fmaf(r.y, py2, fmaf(r.z, pz2, r.w)));
        if (dp < d2) {
            int gm = gbase + m;
            if (dp < d1) {
                d2 = d1; i2 = i1;
                if (dp < d0) { d1 = d0; i1 = i0; d0 = dp; i0 = gm; }
                else         { d1 = dp; i1 = gm; }
            } else { d2 = dp; i2 = gm; }
        }
    }

    size_t base = (((size_t)(b * NN + pt)) * SEG + seg) * 3;
    g_pd[base]     = d0;  g_pi[base]     = i0;
    g_pd[base + 1] = d1;  g_pi[base + 1] = i1;
    g_pd[base + 2] = d2;  g_pi[base + 2] = i2;
}

// ---------------------------------------------------------------------------
// Kernel 1b: merge the SEG partial top-3 lists per point, restore |p|^2,
// compute normalized inverse-distance weights.
// ---------------------------------------------------------------------------
__global__ __launch_bounds__(256) void knn_merge_kernel(const float* __restrict__ coords) {
    int gid = blockIdx.x * 256 + threadIdx.x;      // over BB*NN points

    float d0 = 1e30f, d1 = 1e30f, d2 = 1e30f;
    int   i0 = 0, i1 = 0, i2 = 0;
    size_t pbase = (size_t)gid * SEG * 3;

    #pragma unroll
    for (int s = 0; s < SEG; s++) {
        #pragma unroll
        for (int k = 0; k < 3; k++) {
            float dv = g_pd[pbase + s * 3 + k];
            int   iv = g_pi[pbase + s * 3 + k];
            if (dv < d2) {
                if (dv < d1) {
                    d2 = d1; i2 = i1;
                    if (dv < d0) { d1 = d0; i1 = i0; d0 = dv; i0 = iv; }
                    else         { d1 = dv; i1 = iv; }
                } else { d2 = dv; i2 = iv; }
            }
        }
    }

    const float* cp = coords + (size_t)gid * 3;
    float px = cp[0], py = cp[1], pz = cp[2];
    float pp = px * px + py * py + pz * pz;
    d0 += pp; d1 += pp; d2 += pp;

    float w0 = 1.0f / (d0 + 1e-8f);
    float w1 = 1.0f / (d1 + 1e-8f);
    float w2 = 1.0f / (d2 + 1e-8f);
    float inv = 1.0f / (w0 + w1 + w2);
    size_t base = (size_t)gid * 3;
    g_w[base]     = w0 * inv;
    g_w[base + 1] = w1 * inv;
    g_w[base + 2] = w2 * inv;
    g_idx[base]     = i0;
    g_idx[base + 1] = i1;
    g_idx[base + 2] = i2;
}

// ---------------------------------------------------------------------------
// Kernel 2: fuse ref_features [B,256,M] + ref_t_embed [B,128,M] into a
// channel-contiguous scratch g_featT [B, M, 384] via tiled 32x32 transpose.
// ---------------------------------------------------------------------------
__global__ __launch_bounds__(256) void transpose_kernel(const float* __restrict__ rf,
                                                        const float* __restrict__ rt) {
    __shared__ float tile[32][33];
    int b     = blockIdx.z;
    int mBase = blockIdx.x * 32;
    int cBase = blockIdx.y * 32;
    int tx = threadIdx.x & 31;
    int ty = threadIdx.x >> 5;   // 8 rows

    #pragma unroll
    for (int i = 0; i < 4; i++) {
        int c = cBase + ty + i * 8;
        int m = mBase + tx;
        float v;
        if (c < CF) v = rf[((size_t)b * CF + c) * MM + m];
        else        v = rt[((size_t)b * CT + (c - CF)) * MM + m];
        tile[ty + i * 8][tx] = v;
    }
    __syncthreads();
    #pragma unroll
    for (int i = 0; i < 4; i++) {
        int m = mBase + ty + i * 8;
        int c = cBase + tx;
        g_featT[((size_t)b * MM + m) * CTOT + c] = tile[tx][ty + i * 8];
    }
}

// ---------------------------------------------------------------------------
// Kernel 3: weighted gather of 3 contiguous 384-float rows per query point
// (float4 loads), staged through padded smem [nl][385] (conflict-free both
// directions) so the [B,C,N] output writes are coalesced along n.
// ---------------------------------------------------------------------------
__global__ __launch_bounds__(256) void interp_kernel(float* __restrict__ out) {
    __shared__ float sacc[PTS * (CTOT + 1)];   // [nl][385]
    __shared__ int   sidx[PTS * 3];
    __shared__ float sw[PTS * 3];

    int tid = threadIdx.x;
    int blocksPerB = NN / PTS;           // 1024
    int b  = blockIdx.x / blocksPerB;
    int n0 = (blockIdx.x % blocksPerB) * PTS;

    if (tid < PTS * 3) {
        size_t base = ((size_t)(b * NN + n0)) * 3;
        sidx[tid] = g_idx[base + tid];
        sw[tid]   = g_w[base + tid];
    }
    __syncthreads();

    const float4* ft = (const float4*)(g_featT + (size_t)b * MM * CTOT);
    const int R4 = CTOT / 4;             // 96 float4 per row

    for (int j = tid; j < PTS * R4; j += 256) {
        int nl = j / R4;
        int c4 = j - nl * R4;
        int q  = nl * 3;
        float w0 = sw[q], w1 = sw[q + 1], w2 = sw[q + 2];
        float4 a  = ft[(size_t)sidx[q]     * R4 + c4];
        float4 bv = ft[(size_t)sidx[q + 1] * R4 + c4];
        float4 cv = ft[(size_t)sidx[q + 2] * R4 + c4];
        float* dst = sacc + nl * (CTOT + 1) + c4 * 4;
        dst[0] = fmaf(w0, a.x, fmaf(w1, bv.x, w2 * cv.x));
        dst[1] = fmaf(w0, a.y, fmaf(w1, bv.y, w2 * cv.y));
        dst[2] = fmaf(w0, a.z, fmaf(w1, bv.z, w2 * cv.z));
        dst[3] = fmaf(w0, a.w, fmaf(w1, bv.w, w2 * cv.w));
    }
    __syncthreads();

    float* tout = out + (size_t)BB * 320 * NN;   // t_embed block after features
    for (int j = tid; j < PTS * CTOT; j += 256) {
        int c  = j >> 4;       // / PTS
        int nl = j & 15;
        float v = sacc[nl * (CTOT + 1) + c];
        if (c < CF) out[((size_t)b * 320 + c) * NN + n0 + nl] = v;
        else        tout[((size_t)b * CT + (c - CF)) * NN + n0 + nl] = v;
    }
}

// ---------------------------------------------------------------------------
extern "C" void kernel_launch(void* const* d_in, const int* in_sizes, int n_in,
                              void* d_out, int out_size) {
    const float* coords = (const float*)d_in[0];   // [B, N, 3]
    const float* refc   = (const float*)d_in[1];   // [B, M, 3]
    const float* rf     = (const float*)d_in[2];   // [B, 256, M]
    const float* rt     = (const float*)d_in[3];   // [B, 128, M]
    const float* pf     = (const float*)d_in[4];   // [B, 64, N]
    float* out = (float*)d_out;

    knn_partial_kernel<<<BB * (NN / 128) * SEG, 128>>>(coords, refc);
    knn_merge_kernel<<<BB * NN / 256, 256>>>(coords);

    dim3 tg(MM / 32, CTOT / 32, BB);
    transpose_kernel<<<tg, 256>>>(rf, rt);

    interp_kernel<<<BB * NN / PTS, 256>>>(out);

    // Skip-feature concat: channels 256..319 of the features block are a
    // contiguous copy of points_features per batch.
    for (int b = 0; b < BB; b++) {
        cudaMemcpyAsync(out + ((size_t)b * 320 + 256) * NN,
                        pf + (size_t)b * CP * NN,
                        (size_t)CP * NN * sizeof(float),
                        cudaMemcpyDeviceToDevice);
    }
}